// round 11
// baseline (speedup 1.0000x reference)
#include <cuda_runtime.h>
#include <cuda_bf16.h>
#include <math.h>
#include <stdint.h>

#define BTd 4
#define Ld 512
#define F1Dd 46
#define F2Dd 44
#define Cd 32
#define Kd 64
#define NBLKd 4
#define PWSTRIDE 109   // F2D + 2C + 1
#define KP 48          // K padded for MMA (3 chunks of 16); col44=sep, 45..47=0

// Scratch (device globals; zero-initialized)
__device__ float g_x[BTd * Cd * Ld];
__device__ float g_y[BTd * Cd * Ld];
__device__ float g_eL[BTd * Ld * Kd];
__device__ float g_eR[BTd * Ld * Kd];
__device__ float g_pe[Ld * 32];
__device__ float g_sep[Ld];
__device__ unsigned g_cnt[16];
// W hi/lo bf16 images, [64][KP] row-major (col 44 = wsep, 45..47 = 0)
__device__ __align__(16) unsigned short g_Wh[64 * KP];
__device__ __align__(16) unsigned short g_Wl[64 * KP];

// ---------------------------------------------------------------------------
// tower kernel (proven R6/R10 version; W image now includes wsep at k=44)
// ---------------------------------------------------------------------------
#define NB_TOWER 128u
static __device__ __forceinline__ void grid_bar(int b) {
    __syncthreads();
    if (threadIdx.x == 0) {
        __threadfence();
        unsigned t = atomicAdd(&g_cnt[b], 1u);
        if (t < NB_TOWER - 1u) {
            while (*((volatile unsigned*)&g_cnt[b]) < NB_TOWER) {}
        }
        __threadfence();
        unsigned u = atomicAdd(&g_cnt[b], 1u);
        if (u == 2u * NB_TOWER - 1u) *((volatile unsigned*)&g_cnt[b]) = 0u;
    }
    __syncthreads();
}

static __device__ __forceinline__ float2 blockReduce2(float a, float b) {
    __shared__ float sa[16], sb[16], res[2];
    #pragma unroll
    for (int off = 16; off > 0; off >>= 1) {
        a += __shfl_down_sync(0xffffffffu, a, off);
        b += __shfl_down_sync(0xffffffffu, b, off);
    }
    int wid = threadIdx.x >> 5, lid = threadIdx.x & 31;
    if (lid == 0) { sa[wid] = a; sb[wid] = b; }
    __syncthreads();
    if (threadIdx.x == 0) {
        float ta = 0.f, tb = 0.f;
        #pragma unroll
        for (int i = 0; i < 16; ++i) { ta += sa[i]; tb += sb[i]; }
        res[0] = ta; res[1] = tb;
    }
    __syncthreads();
    return make_float2(res[0], res[1]);
}

static __device__ __forceinline__ float conv_row(const float* __restrict__ xb,
                                                 const float* __restrict__ sw, int l) {
    float a0 = 0.f, a1 = 0.f, a2 = 0.f, a3 = 0.f;
    #pragma unroll
    for (int ci = 0; ci < Cd; ci += 4) {
        #pragma unroll
        for (int q = 0; q < 4; ++q) {
            const float* xr = xb + (ci + q) * Ld;
            float xm = (l > 0)      ? xr[l - 1] : 0.f;
            float x0 = xr[l];
            float xp = (l < Ld - 1) ? xr[l + 1] : 0.f;
            float s = sw[(ci + q) * 3 + 0] * xm + sw[(ci + q) * 3 + 1] * x0
                    + sw[(ci + q) * 3 + 2] * xp;
            if (q == 0) a0 += s; else if (q == 1) a1 += s;
            else if (q == 2) a2 += s; else a3 += s;
        }
    }
    return (a0 + a1) + (a2 + a3);
}

__global__ __launch_bounds__(512) void k_tower(const float* __restrict__ t1d,
                                               const float* __restrict__ p1w,
                                               const float* __restrict__ p1b,
                                               const float* __restrict__ c1w,
                                               const float* __restrict__ c2w,
                                               const float* __restrict__ pw,
                                               const float* __restrict__ pb) {
    __shared__ float shmem[4352];
    const int bid = blockIdx.x;
    const int tid = threadIdx.x;

    if (bid == 0) {   // tables
        int l = tid;
        g_sep[l] = logf((float)l + 1.0f);
        const float c0 = -logf(10000.0f) / 32.0f;
        #pragma unroll
        for (int m = 0; m < 16; ++m) {
            float div = expf((2.0f * m) * c0);
            float a = (float)l * div;
            g_pe[l * 32 + m]      = sinf(a);
            g_pe[l * 32 + 16 + m] = cosf(a);
        }
    }
    if (bid == 127) { // W hi/lo bf16 images [64][KP]; col44 = wsep
        for (int idx = tid; idx < 64 * KP; idx += 512) {
            int n = idx / KP, k = idx - n * KP;
            float v = 0.f;
            if (k < F2Dd)       v = pw[n * PWSTRIDE + k];
            else if (k == F2Dd) v = pw[n * PWSTRIDE + (PWSTRIDE - 1)];
            __nv_bfloat16 h = __float2bfloat16(v);
            float lo = v - __bfloat162float(h);
            g_Wh[idx] = __bfloat16_as_ushort(h);
            g_Wl[idx] = __bfloat16_as_ushort(__float2bfloat16(lo));
        }
    }

    // proj1d
    {
        const int bt = bid >> 5;
        const int l0 = (bid & 31) * 16;
        float* st  = shmem;
        float* swp = shmem + 736;
        const float* tb = t1d + ((size_t)(bt * Ld + l0)) * F1Dd;
        for (int idx = tid; idx < 16 * F1Dd; idx += 512) st[idx] = tb[idx];
        for (int idx = tid; idx < Cd * F1Dd; idx += 512) swp[idx] = p1w[idx];
        __syncthreads();
        const int c = tid >> 4, ll = tid & 15;
        float acc = p1b[c];
        #pragma unroll
        for (int f = 0; f < F1Dd; ++f) acc += swp[c * F1Dd + f] * st[ll * F1Dd + f];
        g_x[(bt * Cd + c) * Ld + l0 + ll] = acc;
    }
    grid_bar(0);

    // conv tower
    {
        const int co = bid & 31;
        const int bt = bid >> 5;
        const int l = tid;
        float* sw = shmem;
        for (int blk = 0; blk < NBLKd; ++blk) {
            if (tid < Cd * 3) sw[tid] = c1w[((size_t)(blk * Cd + co)) * Cd * 3 + tid];
            __syncthreads();
            {
                float acc = conv_row(g_x + bt * Cd * Ld, sw, l);
                float2 s = blockReduce2(acc, acc * acc);
                float m = s.x * (1.0f / Ld);
                float var = s.y * (1.0f / Ld) - m * m;
                float v = (acc - m) * rsqrtf(var + 1e-5f);
                g_y[(bt * Cd + co) * Ld + l] = (v > 0.f) ? v : expm1f(v);
            }
            grid_bar(1 + 2 * blk);
            if (tid < Cd * 3) sw[tid] = c2w[((size_t)(blk * Cd + co)) * Cd * 3 + tid];
            __syncthreads();
            {
                float acc = conv_row(g_y + bt * Cd * Ld, sw, l);
                float2 s = blockReduce2(acc, acc * acc);
                float m = s.x * (1.0f / Ld);
                float var = s.y * (1.0f / Ld) - m * m;
                float v = (acc - m) * rsqrtf(var + 1e-5f);
                int idx = (bt * Cd + co) * Ld + l;
                float xo = g_x[idx] + v;
                g_x[idx] = (xo > 0.f) ? xo : expm1f(xo);
            }
            grid_bar(2 + 2 * blk);
        }
    }

    // eL/eR
    {
        float* sWl = shmem;
        float* sWr = shmem + 64 * 33;
        for (int idx = tid; idx < Kd * 64; idx += 512) {
            int o = idx >> 6, c2 = idx & 63;
            float v = pw[o * PWSTRIDE + F2Dd + c2];
            if (c2 < Cd) sWl[o * 33 + c2] = v;
            else         sWr[o * 33 + (c2 - Cd)] = v;
        }
        __syncthreads();
        const int T = bid * 512 + tid;
        const int o = T & 63;
        const int lbt = T >> 6;
        const int l = lbt & 511;
        const int bh = lbt >> 9;
        const float bias = pb[o];
        #pragma unroll
        for (int bt2 = 0; bt2 < 2; ++bt2) {
            const int bt = bh * 2 + bt2;
            float aL = bias, aR = 0.f;
            #pragma unroll
            for (int c = 0; c < Cd; ++c) {
                float e = g_x[(bt * Cd + c) * Ld + l];
                aL += sWl[o * 33 + c] * e;
                aR += sWr[o * 33 + c] * e;
            }
            g_eL[((size_t)(bt * Ld + l)) * Kd + o] = aL;
            g_eR[((size_t)(bt * Ld + l)) * Kd + o] = aR;
        }
    }
}

// ---------------------------------------------------------------------------
// pair kernel: persistent 4-tile CTA, cp.async prefetch, bf16 hi/lo mma.sync
// ---------------------------------------------------------------------------
static __device__ __forceinline__ uint32_t smem_u32(const void* p) {
    uint32_t a;
    asm("{ .reg .u64 t; cvta.to.shared.u64 t, %1; cvt.u32.u64 %0, t; }" : "=r"(a) : "l"(p));
    return a;
}
static __device__ __forceinline__ uint32_t cvt_bf16x2(float lo, float hi) {
    uint32_t r;  // d.lo = bf16(lo arg), d.hi = bf16(hi arg)
    asm("cvt.rn.satfinite.bf16x2.f32 %0, %1, %2;" : "=r"(r) : "f"(hi), "f"(lo));
    return r;
}
static __device__ __forceinline__ void ldm_x4(uint32_t* r, uint32_t addr) {
    asm volatile("ldmatrix.sync.aligned.m8n8.x4.shared.b16 {%0,%1,%2,%3}, [%4];"
                 : "=r"(r[0]), "=r"(r[1]), "=r"(r[2]), "=r"(r[3]) : "r"(addr));
}
static __device__ __forceinline__ void mma_bf16(float* d, const uint32_t* a,
                                                const uint32_t* b) {
    asm volatile(
        "mma.sync.aligned.m16n8k16.row.col.f32.bf16.bf16.f32 "
        "{%0,%1,%2,%3}, {%4,%5,%6,%7}, {%8,%9}, {%0,%1,%2,%3};"
        : "+f"(d[0]), "+f"(d[1]), "+f"(d[2]), "+f"(d[3])
        : "r"(a[0]), "r"(a[1]), "r"(a[2]), "r"(a[3]), "r"(b[0]), "r"(b[1]));
}
static __device__ __forceinline__ void cp16(uint32_t dst, const void* src) {
    asm volatile("cp.async.cg.shared.global [%0], [%1], 16;" :: "r"(dst), "l"(src));
}

// smem layout (bytes); ARS = bf16 row stride (16B-aligned, ldmatrix-clean)
#define ARS 112
#define PB_HI   0          // 64*112 = 7168
#define PB_LO   7168       // -> 14336
#define PSB     14336      // base[64] f32 -> 14592
#define PABF_HI 14592      // 128*112 = 14336 -> 28928
#define PABF_LO 28928      // -> 43264
// sOut overlays [PABF_HI, PABF_HI+34816) = [14592, 49408): covers ABF + pad
#define PARAW   49408      // 1408*16 = 22528 -> 71936
#define DSMEM   71936
#define SOUTS 68           // sOut row stride in words

__global__ __launch_bounds__(128) void k_pair(const float* __restrict__ t2d,
                                              const float* __restrict__ pw,
                                              float* __restrict__ out) {
    extern __shared__ __align__(16) unsigned char dsm[];
    const int tid = threadIdx.x;
    const int wid = tid >> 5;
    const int lid = tid & 31;
    const uint32_t sbase = smem_u32(dsm);

    const int bidx = blockIdx.x;          // 2048 = bt*512 + i
    const int bt = bidx >> 9;
    const int i  = bidx & 511;
    const size_t ibase = ((size_t)(bt * Ld + i)) * Ld;

    // ---- one-time staging: W images + base(eL + pe_i) ----
    {
        const uint4* wh = (const uint4*)g_Wh;
        const uint4* wl = (const uint4*)g_Wl;
        #pragma unroll
        for (int q = 0; q < 3; ++q) {
            int idx = tid + q * 128;            // 384 = 64 rows * 6
            int r = idx / 6, c = idx - r * 6;
            *(uint4*)(dsm + PB_HI + r * ARS + c * 16) = wh[idx];
            *(uint4*)(dsm + PB_LO + r * ARS + c * 16) = wl[idx];
        }
    }
    if (tid < Kd) {
        float b = g_eL[ibase / Ld * Kd + tid];   // g_eL[(bt*Ld+i)*Kd + tid]
        if (bt == 0 && tid < 32) b += g_pe[i * 32 + tid];
        ((float*)(dsm + PSB))[tid] = b;
    }

    // ---- prefetch tile 0 (raw fp32 t2d rows, contiguous) ----
    {
        const char* src = (const char*)(t2d + ibase * F2Dd);
        #pragma unroll
        for (int it = 0; it < 11; ++it) {
            int idx = tid + it * 128;
            cp16(sbase + PARAW + idx * 16, src + (size_t)idx * 16);
        }
        asm volatile("cp.async.commit_group;" ::: "memory");
    }

    // ldmatrix lane addresses (within A/B bf16 tiles)
    const uint32_t aRow = (uint32_t)(wid * 32 + (lid & 15)) * ARS + (uint32_t)((lid >> 4) * 16);
    const uint32_t bRow = (uint32_t)((lid & 7) + ((lid >> 4) << 3)) * ARS
                        + (uint32_t)(((lid >> 3) & 1) * 16);

    for (int t = 0; t < 4; ++t) {
        const int j0 = t << 7;
        const size_t rowbase = ibase + j0;

        asm volatile("cp.async.wait_group 0;" ::: "memory");
        __syncthreads();

        // ---- convert raw fp32 -> bf16 hi/lo tiles (+ sep fold at col 44) ----
        {
            const float4* araw = (const float4*)(dsm + PARAW);
            #pragma unroll
            for (int it = 0; it < 11; ++it) {
                int idx = tid + it * 128;             // 1408 exactly
                float4 x = araw[idx];
                int r = idx / 11, kq = idx - r * 11;
                uint32_t h0 = cvt_bf16x2(x.x, x.y);
                uint32_t h1 = cvt_bf16x2(x.z, x.w);
                float f00 = __uint_as_float(h0 << 16);
                float f01 = __uint_as_float(h0 & 0xFFFF0000u);
                float f10 = __uint_as_float(h1 << 16);
                float f11 = __uint_as_float(h1 & 0xFFFF0000u);
                uint32_t l0 = cvt_bf16x2(x.x - f00, x.y - f01);
                uint32_t l1 = cvt_bf16x2(x.z - f10, x.w - f11);
                *(uint2*)(dsm + PABF_HI + r * ARS + kq * 8) = make_uint2(h0, h1);
                *(uint2*)(dsm + PABF_LO + r * ARS + kq * 8) = make_uint2(l0, l1);
            }
            // cols 44..47: sep at 44, zeros elsewhere
            float sep = g_sep[abs(i - (j0 + tid))];
            uint32_t sh2 = cvt_bf16x2(sep, 0.f);                 // low half = bf16(sep)
            float shf = __uint_as_float(sh2 << 16);
            uint32_t sl2 = cvt_bf16x2(sep - shf, 0.f);
            *(uint2*)(dsm + PABF_HI + tid * ARS + 88) = make_uint2(sh2 & 0xFFFFu, 0u);
            *(uint2*)(dsm + PABF_LO + tid * ARS + 88) = make_uint2(sl2 & 0xFFFFu, 0u);
        }
        __syncthreads();

        // ---- prefetch next tile (overlaps MMA + epilogue) ----
        if (t < 3) {
            const char* src = (const char*)(t2d + (rowbase + 128) * F2Dd);
            #pragma unroll
            for (int it = 0; it < 11; ++it) {
                int idx = tid + it * 128;
                cp16(sbase + PARAW + idx * 16, src + (size_t)idx * 16);
            }
            asm volatile("cp.async.commit_group;" ::: "memory");
        }

        // ---- MMA: warp w owns rows w*32..+31 (2 m16) x 64 cols ----
        float acc[2][8][4];
        #pragma unroll
        for (int mt = 0; mt < 2; ++mt)
            #pragma unroll
            for (int nt = 0; nt < 8; ++nt)
                #pragma unroll
                for (int e = 0; e < 4; ++e) acc[mt][nt][e] = 0.f;

        #pragma unroll
        for (int kc = 0; kc < 3; ++kc) {
            uint32_t Ah[2][4], Al[2][4];
            ldm_x4(Ah[0], sbase + PABF_HI + aRow + kc * 32);
            ldm_x4(Ah[1], sbase + PABF_HI + aRow + 16 * ARS + kc * 32);
            ldm_x4(Al[0], sbase + PABF_LO + aRow + kc * 32);
            ldm_x4(Al[1], sbase + PABF_LO + aRow + 16 * ARS + kc * 32);
            uint32_t Bh[8][2], Bl[8][2];
            #pragma unroll
            for (int nt2 = 0; nt2 < 4; ++nt2) {
                uint32_t rh[4], rl[4];
                ldm_x4(rh, sbase + PB_HI + bRow + (uint32_t)(nt2 * 16) * ARS + kc * 32);
                ldm_x4(rl, sbase + PB_LO + bRow + (uint32_t)(nt2 * 16) * ARS + kc * 32);
                Bh[nt2 * 2][0] = rh[0]; Bh[nt2 * 2][1] = rh[1];
                Bh[nt2 * 2 + 1][0] = rh[2]; Bh[nt2 * 2 + 1][1] = rh[3];
                Bl[nt2 * 2][0] = rl[0]; Bl[nt2 * 2][1] = rl[1];
                Bl[nt2 * 2 + 1][0] = rl[2]; Bl[nt2 * 2 + 1][1] = rl[3];
            }
            #pragma unroll
            for (int mt = 0; mt < 2; ++mt)
                #pragma unroll
                for (int nt = 0; nt < 8; ++nt) {
                    mma_bf16(acc[mt][nt], Ah[mt], Bh[nt]);
                    mma_bf16(acc[mt][nt], Al[mt], Bh[nt]);
                    mma_bf16(acc[mt][nt], Ah[mt], Bl[nt]);
                }
        }
        __syncthreads();   // ABF smem dead -> reuse as sOut

        // ---- D frags -> sOut[row][o] ----
        {
            float* sOut = (float*)(dsm + PABF_HI);
            #pragma unroll
            for (int mt = 0; mt < 2; ++mt) {
                const int r0 = wid * 32 + mt * 16 + (lid >> 2);
                #pragma unroll
                for (int nt = 0; nt < 8; ++nt) {
                    const int col = nt * 8 + (lid & 3) * 2;
                    *(float2*)(sOut + r0 * SOUTS + col) =
                        make_float2(acc[mt][nt][0], acc[mt][nt][1]);
                    *(float2*)(sOut + (r0 + 8) * SOUTS + col) =
                        make_float2(acc[mt][nt][2], acc[mt][nt][3]);
                }
            }
        }
        __syncthreads();

        // ---- coalesced epilogue ----
        {
            const float* sOut = (const float*)(dsm + PABF_HI);
            const float* sBase = (const float*)(dsm + PSB);
            const int f4 = tid & 15, h = tid >> 4;
            const int o4 = f4 * 4;
            float4 b4 = *(const float4*)(sBase + o4);
            const bool peJ = (bt == 0) && (f4 >= 8);
            #pragma unroll
            for (int rr = 0; rr < 16; ++rr) {
                const int row = rr * 8 + h;
                const int j = j0 + row;
                float4 v = *(const float4*)(sOut + row * SOUTS + o4);
                float4 r4 = *(const float4*)(g_eR + ((size_t)(bt * Ld + j)) * Kd + o4);
                v.x += b4.x + r4.x;
                v.y += b4.y + r4.y;
                v.z += b4.z + r4.z;
                v.w += b4.w + r4.w;
                if (peJ) {
                    float4 p4 = *(const float4*)(g_pe + j * 32 + (o4 - 32));
                    v.x += p4.x; v.y += p4.y; v.z += p4.z; v.w += p4.w;
                }
                __stcs((float4*)(out + (rowbase + row) * Kd + o4), v);
            }
        }
        __syncthreads();   // sOut fully read before next tile's convert overwrites
    }
}

// ---------------------------------------------------------------------------
extern "C" void kernel_launch(void* const* d_in, const int* in_sizes, int n_in,
                              void* d_out, int out_size) {
    const float* t1d = (const float*)d_in[0];
    const float* t2d = (const float*)d_in[1];
    const float* p1w = (const float*)d_in[2];
    const float* p1b = (const float*)d_in[3];
    const float* c1w = (const float*)d_in[4];
    const float* c2w = (const float*)d_in[5];
    const float* pw  = (const float*)d_in[6];
    const float* pb  = (const float*)d_in[7];
    float* out = (float*)d_out;
    (void)in_sizes; (void)n_in; (void)out_size;

    static int attr_set = 0;
    if (!attr_set) {
        cudaFuncSetAttribute(k_pair, cudaFuncAttributeMaxDynamicSharedMemorySize, DSMEM);
        attr_set = 1;
    }
    k_tower<<<128, 512>>>(t1d, p1w, p1b, c1w, c2w, pw, pb);
    k_pair<<<2048, 128, DSMEM>>>(t2d, pw, out);
}

// round 12
// speedup vs baseline: 1.3284x; 1.3284x over previous
#include <cuda_runtime.h>
#include <cuda_bf16.h>
#include <math.h>
#include <stdint.h>

#define BTd 4
#define Ld 512
#define F1Dd 46
#define F2Dd 44
#define Cd 32
#define Kd 64
#define NBLKd 4
#define PWSTRIDE 109   // F2D + 2C + 1
#define KP 48          // K padded (3 chunks of 16); col 44 = sep/wsep, 45..47 = 0

// Scratch (device globals; zero-initialized)
__device__ float g_x[BTd * Cd * Ld];
__device__ float g_y[BTd * Cd * Ld];
__device__ float g_eL[BTd * Ld * Kd];
__device__ float g_eR[BTd * Ld * Kd];
__device__ float g_pe[Ld * 32];
__device__ float g_sep[Ld];
__device__ unsigned g_cnt[16];
// W hi/lo bf16 images, [64][KP] row-major (col 44 = wsep, 45..47 = 0)
__device__ __align__(16) unsigned short g_Wh[64 * KP];
__device__ __align__(16) unsigned short g_Wl[64 * KP];

// ---------------------------------------------------------------------------
// tower kernel (proven; W image includes wsep at k=44)
// ---------------------------------------------------------------------------
#define NB_TOWER 128u
static __device__ __forceinline__ void grid_bar(int b) {
    __syncthreads();
    if (threadIdx.x == 0) {
        __threadfence();
        unsigned t = atomicAdd(&g_cnt[b], 1u);
        if (t < NB_TOWER - 1u) {
            while (*((volatile unsigned*)&g_cnt[b]) < NB_TOWER) {}
        }
        __threadfence();
        unsigned u = atomicAdd(&g_cnt[b], 1u);
        if (u == 2u * NB_TOWER - 1u) *((volatile unsigned*)&g_cnt[b]) = 0u;
    }
    __syncthreads();
}

static __device__ __forceinline__ float2 blockReduce2(float a, float b) {
    __shared__ float sa[16], sb[16], res[2];
    #pragma unroll
    for (int off = 16; off > 0; off >>= 1) {
        a += __shfl_down_sync(0xffffffffu, a, off);
        b += __shfl_down_sync(0xffffffffu, b, off);
    }
    int wid = threadIdx.x >> 5, lid = threadIdx.x & 31;
    if (lid == 0) { sa[wid] = a; sb[wid] = b; }
    __syncthreads();
    if (threadIdx.x == 0) {
        float ta = 0.f, tb = 0.f;
        #pragma unroll
        for (int i = 0; i < 16; ++i) { ta += sa[i]; tb += sb[i]; }
        res[0] = ta; res[1] = tb;
    }
    __syncthreads();
    return make_float2(res[0], res[1]);
}

static __device__ __forceinline__ float conv_row(const float* __restrict__ xb,
                                                 const float* __restrict__ sw, int l) {
    float a0 = 0.f, a1 = 0.f, a2 = 0.f, a3 = 0.f;
    #pragma unroll
    for (int ci = 0; ci < Cd; ci += 4) {
        #pragma unroll
        for (int q = 0; q < 4; ++q) {
            const float* xr = xb + (ci + q) * Ld;
            float xm = (l > 0)      ? xr[l - 1] : 0.f;
            float x0 = xr[l];
            float xp = (l < Ld - 1) ? xr[l + 1] : 0.f;
            float s = sw[(ci + q) * 3 + 0] * xm + sw[(ci + q) * 3 + 1] * x0
                    + sw[(ci + q) * 3 + 2] * xp;
            if (q == 0) a0 += s; else if (q == 1) a1 += s;
            else if (q == 2) a2 += s; else a3 += s;
        }
    }
    return (a0 + a1) + (a2 + a3);
}

__global__ __launch_bounds__(512) void k_tower(const float* __restrict__ t1d,
                                               const float* __restrict__ p1w,
                                               const float* __restrict__ p1b,
                                               const float* __restrict__ c1w,
                                               const float* __restrict__ c2w,
                                               const float* __restrict__ pw,
                                               const float* __restrict__ pb) {
    __shared__ float shmem[4352];
    const int bid = blockIdx.x;
    const int tid = threadIdx.x;

    if (bid == 0) {   // tables
        int l = tid;
        g_sep[l] = logf((float)l + 1.0f);
        const float c0 = -logf(10000.0f) / 32.0f;
        #pragma unroll
        for (int m = 0; m < 16; ++m) {
            float div = expf((2.0f * m) * c0);
            float a = (float)l * div;
            g_pe[l * 32 + m]      = sinf(a);
            g_pe[l * 32 + 16 + m] = cosf(a);
        }
    }
    if (bid == 127) { // W hi/lo bf16 images [64][KP]; col44 = wsep
        for (int idx = tid; idx < 64 * KP; idx += 512) {
            int n = idx / KP, k = idx - n * KP;
            float v = 0.f;
            if (k < F2Dd)       v = pw[n * PWSTRIDE + k];
            else if (k == F2Dd) v = pw[n * PWSTRIDE + (PWSTRIDE - 1)];
            __nv_bfloat16 h = __float2bfloat16(v);
            float lo = v - __bfloat162float(h);
            g_Wh[idx] = __bfloat16_as_ushort(h);
            g_Wl[idx] = __bfloat16_as_ushort(__float2bfloat16(lo));
        }
    }

    // proj1d
    {
        const int bt = bid >> 5;
        const int l0 = (bid & 31) * 16;
        float* st  = shmem;
        float* swp = shmem + 736;
        const float* tb = t1d + ((size_t)(bt * Ld + l0)) * F1Dd;
        for (int idx = tid; idx < 16 * F1Dd; idx += 512) st[idx] = tb[idx];
        for (int idx = tid; idx < Cd * F1Dd; idx += 512) swp[idx] = p1w[idx];
        __syncthreads();
        const int c = tid >> 4, ll = tid & 15;
        float acc = p1b[c];
        #pragma unroll
        for (int f = 0; f < F1Dd; ++f) acc += swp[c * F1Dd + f] * st[ll * F1Dd + f];
        g_x[(bt * Cd + c) * Ld + l0 + ll] = acc;
    }
    grid_bar(0);

    // conv tower
    {
        const int co = bid & 31;
        const int bt = bid >> 5;
        const int l = tid;
        float* sw = shmem;
        for (int blk = 0; blk < NBLKd; ++blk) {
            if (tid < Cd * 3) sw[tid] = c1w[((size_t)(blk * Cd + co)) * Cd * 3 + tid];
            __syncthreads();
            {
                float acc = conv_row(g_x + bt * Cd * Ld, sw, l);
                float2 s = blockReduce2(acc, acc * acc);
                float m = s.x * (1.0f / Ld);
                float var = s.y * (1.0f / Ld) - m * m;
                float v = (acc - m) * rsqrtf(var + 1e-5f);
                g_y[(bt * Cd + co) * Ld + l] = (v > 0.f) ? v : expm1f(v);
            }
            grid_bar(1 + 2 * blk);
            if (tid < Cd * 3) sw[tid] = c2w[((size_t)(blk * Cd + co)) * Cd * 3 + tid];
            __syncthreads();
            {
                float acc = conv_row(g_y + bt * Cd * Ld, sw, l);
                float2 s = blockReduce2(acc, acc * acc);
                float m = s.x * (1.0f / Ld);
                float var = s.y * (1.0f / Ld) - m * m;
                float v = (acc - m) * rsqrtf(var + 1e-5f);
                int idx = (bt * Cd + co) * Ld + l;
                float xo = g_x[idx] + v;
                g_x[idx] = (xo > 0.f) ? xo : expm1f(xo);
            }
            grid_bar(2 + 2 * blk);
        }
    }

    // eL/eR
    {
        float* sWl = shmem;
        float* sWr = shmem + 64 * 33;
        for (int idx = tid; idx < Kd * 64; idx += 512) {
            int o = idx >> 6, c2 = idx & 63;
            float v = pw[o * PWSTRIDE + F2Dd + c2];
            if (c2 < Cd) sWl[o * 33 + c2] = v;
            else         sWr[o * 33 + (c2 - Cd)] = v;
        }
        __syncthreads();
        const int T = bid * 512 + tid;
        const int o = T & 63;
        const int lbt = T >> 6;
        const int l = lbt & 511;
        const int bh = lbt >> 9;
        const float bias = pb[o];
        #pragma unroll
        for (int bt2 = 0; bt2 < 2; ++bt2) {
            const int bt = bh * 2 + bt2;
            float aL = bias, aR = 0.f;
            #pragma unroll
            for (int c = 0; c < Cd; ++c) {
                float e = g_x[(bt * Cd + c) * Ld + l];
                aL += sWl[o * 33 + c] * e;
                aR += sWr[o * 33 + c] * e;
            }
            g_eL[((size_t)(bt * Ld + l)) * Kd + o] = aL;
            g_eR[((size_t)(bt * Ld + l)) * Kd + o] = aR;
        }
    }
}

// ---------------------------------------------------------------------------
// pair kernel v6: direct-load A fragments (no A smem), direct-store epilogue
// (no sOut). smem = B hi/lo images + base table only (static, 14.6 KB).
// ---------------------------------------------------------------------------
static __device__ __forceinline__ uint32_t smem_u32(const void* p) {
    uint32_t a;
    asm("{ .reg .u64 t; cvta.to.shared.u64 t, %1; cvt.u32.u64 %0, t; }" : "=r"(a) : "l"(p));
    return a;
}
static __device__ __forceinline__ uint32_t cvt_bf16x2(float lo, float hi) {
    uint32_t r;  // d.lo = bf16(lo arg), d.hi = bf16(hi arg)
    asm("cvt.rn.satfinite.bf16x2.f32 %0, %1, %2;" : "=r"(r) : "f"(hi), "f"(lo));
    return r;
}
static __device__ __forceinline__ void ldm_x4(uint32_t* r, uint32_t addr) {
    asm volatile("ldmatrix.sync.aligned.m8n8.x4.shared.b16 {%0,%1,%2,%3}, [%4];"
                 : "=r"(r[0]), "=r"(r[1]), "=r"(r[2]), "=r"(r[3]) : "r"(addr));
}
static __device__ __forceinline__ void mma_bf16(float* d, const uint32_t* a,
                                                const uint32_t* b) {
    asm volatile(
        "mma.sync.aligned.m16n8k16.row.col.f32.bf16.bf16.f32 "
        "{%0,%1,%2,%3}, {%4,%5,%6,%7}, {%8,%9}, {%0,%1,%2,%3};"
        : "+f"(d[0]), "+f"(d[1]), "+f"(d[2]), "+f"(d[3])
        : "r"(a[0]), "r"(a[1]), "r"(a[2]), "r"(a[3]), "r"(b[0]), "r"(b[1]));
}
// split a float2 into hi/lo bf16x2 regs
static __device__ __forceinline__ void hilo2(float2 x, uint32_t& h, uint32_t& l) {
    h = cvt_bf16x2(x.x, x.y);
    float fx = __uint_as_float(h << 16);
    float fy = __uint_as_float(h & 0xFFFF0000u);
    l = cvt_bf16x2(x.x - fx, x.y - fy);
}

#define ARS 112   // B smem row stride (bytes)

__global__ __launch_bounds__(128, 4) void k_pair(const float* __restrict__ t2d,
                                                 const float* __restrict__ pw,
                                                 float* __restrict__ out) {
    __shared__ __align__(16) unsigned char sB[2 * 64 * ARS];  // hi then lo
    __shared__ __align__(16) float sBase[Kd];
    const int tid = threadIdx.x;
    const int wid = tid >> 5;
    const int lid = tid & 31;
    const int lg  = lid >> 2;     // lane group 0..7 (row within 8)
    const int lt  = lid & 3;      // 0..3 (k/n pair select)
    const uint32_t sbB = smem_u32(sB);

    const int bidx = blockIdx.x;
    const int bt = bidx >> 11;
    const int i  = (bidx >> 2) & 511;
    const int j0 = (bidx & 3) << 7;
    const size_t rowbase = ((size_t)(bt * Ld + i)) * Ld + j0;

    // ---- stage B images + base table ----
    {
        const uint4* wh = (const uint4*)g_Wh;
        const uint4* wl = (const uint4*)g_Wl;
        #pragma unroll
        for (int q = 0; q < 3; ++q) {
            int idx = tid + q * 128;            // 384 = 64 rows * 6
            int r = idx / 6, c = idx - r * 6;
            *(uint4*)(sB + r * ARS + c * 16) = wh[idx];
            *(uint4*)(sB + 64 * ARS + r * ARS + c * 16) = wl[idx];
        }
    }
    if (tid < Kd) {
        float b = g_eL[((size_t)(bt * Ld + i)) * Kd + tid];
        if (bt == 0 && tid < 32) b += g_pe[i * 32 + tid];
        sBase[tid] = b;
    }
    __syncthreads();

    // B ldmatrix lane address (within a 64xARS image)
    const uint32_t bRow = (uint32_t)((lid & 7) + ((lid >> 4) << 3)) * ARS
                        + (uint32_t)(((lid >> 3) & 1) * 16);

    // A row indices for this lane (local j within tile)
    const int ar0 = wid * 32 + lg;        // mt=0 rows: ar0, ar0+8
    const int ar1 = ar0 + 16;             // mt=1 rows: ar1, ar1+8
    const float* At = t2d + rowbase * F2Dd;
    // sep values (folded into GEMM at k=44), needed when lt==2
    float sepv[4];
    sepv[0] = g_sep[abs(i - (int)(j0 + ar0))];
    sepv[1] = g_sep[abs(i - (int)(j0 + ar0 + 8))];
    sepv[2] = g_sep[abs(i - (int)(j0 + ar1))];
    sepv[3] = g_sep[abs(i - (int)(j0 + ar1 + 8))];

    float acc[2][8][4];
    #pragma unroll
    for (int mt = 0; mt < 2; ++mt)
        #pragma unroll
        for (int nt = 0; nt < 8; ++nt)
            #pragma unroll
            for (int e = 0; e < 4; ++e) acc[mt][nt][e] = 0.f;

    #pragma unroll
    for (int kc = 0; kc < 3; ++kc) {
        const int k0 = kc * 16 + lt * 2;
        // ---- A fragments direct from global (hi/lo) ----
        uint32_t Ah[2][4], Al[2][4];
        #pragma unroll
        for (int mt = 0; mt < 2; ++mt) {
            const int r0 = (mt == 0) ? ar0 : ar1;
            float2 p0a = *(const float2*)(At + (size_t)r0 * F2Dd + k0);
            float2 p0b = *(const float2*)(At + (size_t)(r0 + 8) * F2Dd + k0);
            float2 p1a, p1b;
            if (kc < 2) {
                p1a = *(const float2*)(At + (size_t)r0 * F2Dd + k0 + 8);
                p1b = *(const float2*)(At + (size_t)(r0 + 8) * F2Dd + k0 + 8);
            } else {
                if (lt < 2) {
                    p1a = *(const float2*)(At + (size_t)r0 * F2Dd + k0 + 8);
                    p1b = *(const float2*)(At + (size_t)(r0 + 8) * F2Dd + k0 + 8);
                } else if (lt == 2) {   // k = 44,45 -> (sep, 0)
                    p1a = make_float2(sepv[mt * 2], 0.f);
                    p1b = make_float2(sepv[mt * 2 + 1], 0.f);
                } else {                // k = 46,47 -> zeros
                    p1a = make_float2(0.f, 0.f);
                    p1b = make_float2(0.f, 0.f);
                }
            }
            hilo2(p0a, Ah[mt][0], Al[mt][0]);
            hilo2(p0b, Ah[mt][1], Al[mt][1]);
            hilo2(p1a, Ah[mt][2], Al[mt][2]);
            hilo2(p1b, Ah[mt][3], Al[mt][3]);
        }
        // ---- B fragments via ldmatrix ----
        uint32_t Bh[8][2], Bl[8][2];
        #pragma unroll
        for (int nt2 = 0; nt2 < 4; ++nt2) {
            uint32_t rh[4], rl[4];
            ldm_x4(rh, sbB + bRow + (uint32_t)(nt2 * 16) * ARS + kc * 32);
            ldm_x4(rl, sbB + 64 * ARS + bRow + (uint32_t)(nt2 * 16) * ARS + kc * 32);
            Bh[nt2 * 2][0] = rh[0]; Bh[nt2 * 2][1] = rh[1];
            Bh[nt2 * 2 + 1][0] = rh[2]; Bh[nt2 * 2 + 1][1] = rh[3];
            Bl[nt2 * 2][0] = rl[0]; Bl[nt2 * 2][1] = rl[1];
            Bl[nt2 * 2 + 1][0] = rl[2]; Bl[nt2 * 2 + 1][1] = rl[3];
        }
        #pragma unroll
        for (int mt = 0; mt < 2; ++mt)
            #pragma unroll
            for (int nt = 0; nt < 8; ++nt) {
                mma_bf16(acc[mt][nt], Ah[mt], Bh[nt]);
                mma_bf16(acc[mt][nt], Al[mt], Bh[nt]);
                mma_bf16(acc[mt][nt], Ah[mt], Bl[nt]);
            }
    }

    // ---- direct epilogue from D fragments ----
    const float* eRb = g_eR + ((size_t)bt * Ld) * Kd;
    float* outb = out + rowbase * Kd;
    #pragma unroll
    for (int mt = 0; mt < 2; ++mt) {
        const int r0 = (mt == 0) ? ar0 : ar1;     // local row (j - j0)
        const int jA = j0 + r0;
        const int jB = jA + 8;
        #pragma unroll
        for (int nt = 0; nt < 8; ++nt) {
            const int col = nt * 8 + lt * 2;
            float2 b2 = *(const float2*)(sBase + col);
            float2 eA = *(const float2*)(eRb + (size_t)jA * Kd + col);
            float2 eB = *(const float2*)(eRb + (size_t)jB * Kd + col);
            float v0 = acc[mt][nt][0] + b2.x + eA.x;
            float v1 = acc[mt][nt][1] + b2.y + eA.y;
            float v2 = acc[mt][nt][2] + b2.x + eB.x;
            float v3 = acc[mt][nt][3] + b2.y + eB.y;
            if (bt == 0 && nt >= 4) {
                float2 pA = *(const float2*)(g_pe + jA * 32 + (col - 32));
                float2 pB = *(const float2*)(g_pe + jB * 32 + (col - 32));
                v0 += pA.x; v1 += pA.y; v2 += pB.x; v3 += pB.y;
            }
            __stcs((float2*)(outb + (size_t)r0 * Kd + col), make_float2(v0, v1));
            __stcs((float2*)(outb + (size_t)(r0 + 8) * Kd + col), make_float2(v2, v3));
        }
    }
}

// ---------------------------------------------------------------------------
extern "C" void kernel_launch(void* const* d_in, const int* in_sizes, int n_in,
                              void* d_out, int out_size) {
    const float* t1d = (const float*)d_in[0];
    const float* t2d = (const float*)d_in[1];
    const float* p1w = (const float*)d_in[2];
    const float* p1b = (const float*)d_in[3];
    const float* c1w = (const float*)d_in[4];
    const float* c2w = (const float*)d_in[5];
    const float* pw  = (const float*)d_in[6];
    const float* pb  = (const float*)d_in[7];
    float* out = (float*)d_out;
    (void)in_sizes; (void)n_in; (void)out_size;

    k_tower<<<128, 512>>>(t1d, p1w, p1b, c1w, c2w, pw, pb);
    k_pair<<<8192, 128>>>(t2d, pw, out);
}

// round 13
// speedup vs baseline: 1.3373x; 1.0067x over previous
#include <cuda_runtime.h>
#include <cuda_bf16.h>
#include <math.h>
#include <stdint.h>

#define BTd 4
#define Ld 512
#define F1Dd 46
#define F2Dd 44
#define Cd 32
#define Kd 64
#define NBLKd 4
#define PWSTRIDE 109   // F2D + 2C + 1
#define KP 48          // K padded (3 chunks of 16); col 44 = sep/wsep, 45..47 = 0

// Scratch (device globals; zero-initialized)
__device__ float g_x[BTd * Cd * Ld];
__device__ float g_y[BTd * Cd * Ld];
__device__ float g_eL[BTd * Ld * Kd];
__device__ float g_eR[BTd * Ld * Kd];
__device__ float g_pe[Ld * 32];
__device__ float g_sep[Ld];
__device__ unsigned g_cnt[16];
// W hi/lo bf16 images, [64][KP] row-major (col 44 = wsep, 45..47 = 0)
__device__ __align__(16) unsigned short g_Wh[64 * KP];
__device__ __align__(16) unsigned short g_Wl[64 * KP];

// ---------------------------------------------------------------------------
// tower kernel (proven; W image includes wsep at k=44)
// ---------------------------------------------------------------------------
#define NB_TOWER 128u
static __device__ __forceinline__ void grid_bar(int b) {
    __syncthreads();
    if (threadIdx.x == 0) {
        __threadfence();
        unsigned t = atomicAdd(&g_cnt[b], 1u);
        if (t < NB_TOWER - 1u) {
            while (*((volatile unsigned*)&g_cnt[b]) < NB_TOWER) {}
        }
        __threadfence();
        unsigned u = atomicAdd(&g_cnt[b], 1u);
        if (u == 2u * NB_TOWER - 1u) *((volatile unsigned*)&g_cnt[b]) = 0u;
    }
    __syncthreads();
}

static __device__ __forceinline__ float2 blockReduce2(float a, float b) {
    __shared__ float sa[16], sb[16], res[2];
    #pragma unroll
    for (int off = 16; off > 0; off >>= 1) {
        a += __shfl_down_sync(0xffffffffu, a, off);
        b += __shfl_down_sync(0xffffffffu, b, off);
    }
    int wid = threadIdx.x >> 5, lid = threadIdx.x & 31;
    if (lid == 0) { sa[wid] = a; sb[wid] = b; }
    __syncthreads();
    if (threadIdx.x == 0) {
        float ta = 0.f, tb = 0.f;
        #pragma unroll
        for (int i = 0; i < 16; ++i) { ta += sa[i]; tb += sb[i]; }
        res[0] = ta; res[1] = tb;
    }
    __syncthreads();
    return make_float2(res[0], res[1]);
}

static __device__ __forceinline__ float conv_row(const float* __restrict__ xb,
                                                 const float* __restrict__ sw, int l) {
    float a0 = 0.f, a1 = 0.f, a2 = 0.f, a3 = 0.f;
    #pragma unroll
    for (int ci = 0; ci < Cd; ci += 4) {
        #pragma unroll
        for (int q = 0; q < 4; ++q) {
            const float* xr = xb + (ci + q) * Ld;
            float xm = (l > 0)      ? xr[l - 1] : 0.f;
            float x0 = xr[l];
            float xp = (l < Ld - 1) ? xr[l + 1] : 0.f;
            float s = sw[(ci + q) * 3 + 0] * xm + sw[(ci + q) * 3 + 1] * x0
                    + sw[(ci + q) * 3 + 2] * xp;
            if (q == 0) a0 += s; else if (q == 1) a1 += s;
            else if (q == 2) a2 += s; else a3 += s;
        }
    }
    return (a0 + a1) + (a2 + a3);
}

__global__ __launch_bounds__(512) void k_tower(const float* __restrict__ t1d,
                                               const float* __restrict__ p1w,
                                               const float* __restrict__ p1b,
                                               const float* __restrict__ c1w,
                                               const float* __restrict__ c2w,
                                               const float* __restrict__ pw,
                                               const float* __restrict__ pb) {
    __shared__ float shmem[4352];
    const int bid = blockIdx.x;
    const int tid = threadIdx.x;

    if (bid == 0) {   // tables
        int l = tid;
        g_sep[l] = logf((float)l + 1.0f);
        const float c0 = -logf(10000.0f) / 32.0f;
        #pragma unroll
        for (int m = 0; m < 16; ++m) {
            float div = expf((2.0f * m) * c0);
            float a = (float)l * div;
            g_pe[l * 32 + m]      = sinf(a);
            g_pe[l * 32 + 16 + m] = cosf(a);
        }
    }
    if (bid == 127) { // W hi/lo bf16 images [64][KP]; col44 = wsep
        for (int idx = tid; idx < 64 * KP; idx += 512) {
            int n = idx / KP, k = idx - n * KP;
            float v = 0.f;
            if (k < F2Dd)       v = pw[n * PWSTRIDE + k];
            else if (k == F2Dd) v = pw[n * PWSTRIDE + (PWSTRIDE - 1)];
            __nv_bfloat16 h = __float2bfloat16(v);
            float lo = v - __bfloat162float(h);
            g_Wh[idx] = __bfloat16_as_ushort(h);
            g_Wl[idx] = __bfloat16_as_ushort(__float2bfloat16(lo));
        }
    }

    // proj1d
    {
        const int bt = bid >> 5;
        const int l0 = (bid & 31) * 16;
        float* st  = shmem;
        float* swp = shmem + 736;
        const float* tb = t1d + ((size_t)(bt * Ld + l0)) * F1Dd;
        for (int idx = tid; idx < 16 * F1Dd; idx += 512) st[idx] = tb[idx];
        for (int idx = tid; idx < Cd * F1Dd; idx += 512) swp[idx] = p1w[idx];
        __syncthreads();
        const int c = tid >> 4, ll = tid & 15;
        float acc = p1b[c];
        #pragma unroll
        for (int f = 0; f < F1Dd; ++f) acc += swp[c * F1Dd + f] * st[ll * F1Dd + f];
        g_x[(bt * Cd + c) * Ld + l0 + ll] = acc;
    }
    grid_bar(0);

    // conv tower
    {
        const int co = bid & 31;
        const int bt = bid >> 5;
        const int l = tid;
        float* sw = shmem;
        for (int blk = 0; blk < NBLKd; ++blk) {
            if (tid < Cd * 3) sw[tid] = c1w[((size_t)(blk * Cd + co)) * Cd * 3 + tid];
            __syncthreads();
            {
                float acc = conv_row(g_x + bt * Cd * Ld, sw, l);
                float2 s = blockReduce2(acc, acc * acc);
                float m = s.x * (1.0f / Ld);
                float var = s.y * (1.0f / Ld) - m * m;
                float v = (acc - m) * rsqrtf(var + 1e-5f);
                g_y[(bt * Cd + co) * Ld + l] = (v > 0.f) ? v : expm1f(v);
            }
            grid_bar(1 + 2 * blk);
            if (tid < Cd * 3) sw[tid] = c2w[((size_t)(blk * Cd + co)) * Cd * 3 + tid];
            __syncthreads();
            {
                float acc = conv_row(g_y + bt * Cd * Ld, sw, l);
                float2 s = blockReduce2(acc, acc * acc);
                float m = s.x * (1.0f / Ld);
                float var = s.y * (1.0f / Ld) - m * m;
                float v = (acc - m) * rsqrtf(var + 1e-5f);
                int idx = (bt * Cd + co) * Ld + l;
                float xo = g_x[idx] + v;
                g_x[idx] = (xo > 0.f) ? xo : expm1f(xo);
            }
            grid_bar(2 + 2 * blk);
        }
    }

    // eL/eR
    {
        float* sWl = shmem;
        float* sWr = shmem + 64 * 33;
        for (int idx = tid; idx < Kd * 64; idx += 512) {
            int o = idx >> 6, c2 = idx & 63;
            float v = pw[o * PWSTRIDE + F2Dd + c2];
            if (c2 < Cd) sWl[o * 33 + c2] = v;
            else         sWr[o * 33 + (c2 - Cd)] = v;
        }
        __syncthreads();
        const int T = bid * 512 + tid;
        const int o = T & 63;
        const int lbt = T >> 6;
        const int l = lbt & 511;
        const int bh = lbt >> 9;
        const float bias = pb[o];
        #pragma unroll
        for (int bt2 = 0; bt2 < 2; ++bt2) {
            const int bt = bh * 2 + bt2;
            float aL = bias, aR = 0.f;
            #pragma unroll
            for (int c = 0; c < Cd; ++c) {
                float e = g_x[(bt * Cd + c) * Ld + l];
                aL += sWl[o * 33 + c] * e;
                aR += sWr[o * 33 + c] * e;
            }
            g_eL[((size_t)(bt * Ld + l)) * Kd + o] = aL;
            g_eR[((size_t)(bt * Ld + l)) * Kd + o] = aR;
        }
    }
}

// ---------------------------------------------------------------------------
// pair kernel v7: direct-load A frags, interleaved B consumption (low regs),
// 5 CTAs/SM target.
// ---------------------------------------------------------------------------
static __device__ __forceinline__ uint32_t smem_u32(const void* p) {
    uint32_t a;
    asm("{ .reg .u64 t; cvta.to.shared.u64 t, %1; cvt.u32.u64 %0, t; }" : "=r"(a) : "l"(p));
    return a;
}
static __device__ __forceinline__ uint32_t cvt_bf16x2(float lo, float hi) {
    uint32_t r;  // d.lo = bf16(lo arg), d.hi = bf16(hi arg)
    asm("cvt.rn.satfinite.bf16x2.f32 %0, %1, %2;" : "=r"(r) : "f"(hi), "f"(lo));
    return r;
}
static __device__ __forceinline__ void ldm_x4(uint32_t* r, uint32_t addr) {
    asm volatile("ldmatrix.sync.aligned.m8n8.x4.shared.b16 {%0,%1,%2,%3}, [%4];"
                 : "=r"(r[0]), "=r"(r[1]), "=r"(r[2]), "=r"(r[3]) : "r"(addr));
}
static __device__ __forceinline__ void mma_bf16(float* d, const uint32_t* a,
                                                const uint32_t* b) {
    asm volatile(
        "mma.sync.aligned.m16n8k16.row.col.f32.bf16.bf16.f32 "
        "{%0,%1,%2,%3}, {%4,%5,%6,%7}, {%8,%9}, {%0,%1,%2,%3};"
        : "+f"(d[0]), "+f"(d[1]), "+f"(d[2]), "+f"(d[3])
        : "r"(a[0]), "r"(a[1]), "r"(a[2]), "r"(a[3]), "r"(b[0]), "r"(b[1]));
}
// split a float2 into hi/lo bf16x2 regs
static __device__ __forceinline__ void hilo2(float2 x, uint32_t& h, uint32_t& l) {
    h = cvt_bf16x2(x.x, x.y);
    float fx = __uint_as_float(h << 16);
    float fy = __uint_as_float(h & 0xFFFF0000u);
    l = cvt_bf16x2(x.x - fx, x.y - fy);
}

#define ARS 112   // B smem row stride (bytes)

__global__ __launch_bounds__(128, 5) void k_pair(const float* __restrict__ t2d,
                                                 const float* __restrict__ pw,
                                                 float* __restrict__ out) {
    __shared__ __align__(16) unsigned char sB[2 * 64 * ARS];  // hi then lo
    __shared__ __align__(16) float sBase[Kd];
    const int tid = threadIdx.x;
    const int wid = tid >> 5;
    const int lid = tid & 31;
    const int lg  = lid >> 2;     // lane group 0..7 (row within 8)
    const int lt  = lid & 3;      // 0..3 (k/n pair select)
    const uint32_t sbB = smem_u32(sB);

    const int bidx = blockIdx.x;
    const int bt = bidx >> 11;
    const int i  = (bidx >> 2) & 511;
    const int j0 = (bidx & 3) << 7;
    const size_t rowbase = ((size_t)(bt * Ld + i)) * Ld + j0;

    // ---- stage B images + base table ----
    {
        const uint4* wh = (const uint4*)g_Wh;
        const uint4* wl = (const uint4*)g_Wl;
        #pragma unroll
        for (int q = 0; q < 3; ++q) {
            int idx = tid + q * 128;            // 384 = 64 rows * 6
            int r = idx / 6, c = idx - r * 6;
            *(uint4*)(sB + r * ARS + c * 16) = wh[idx];
            *(uint4*)(sB + 64 * ARS + r * ARS + c * 16) = wl[idx];
        }
    }
    if (tid < Kd) {
        float b = g_eL[((size_t)(bt * Ld + i)) * Kd + tid];
        if (bt == 0 && tid < 32) b += g_pe[i * 32 + tid];
        sBase[tid] = b;
    }
    __syncthreads();

    // B ldmatrix lane address (within a 64xARS image)
    const uint32_t bRow = (uint32_t)((lid & 7) + ((lid >> 4) << 3)) * ARS
                        + (uint32_t)(((lid >> 3) & 1) * 16);

    // A row indices for this lane (local j within tile)
    const int ar0 = wid * 32 + lg;        // mt=0 rows: ar0, ar0+8
    const int ar1 = ar0 + 16;             // mt=1 rows: ar1, ar1+8
    const float* At = t2d + rowbase * F2Dd;
    // sep values (folded into GEMM at k=44), substituted when lt==2
    float sepv[4];
    sepv[0] = g_sep[abs(i - (int)(j0 + ar0))];
    sepv[1] = g_sep[abs(i - (int)(j0 + ar0 + 8))];
    sepv[2] = g_sep[abs(i - (int)(j0 + ar1))];
    sepv[3] = g_sep[abs(i - (int)(j0 + ar1 + 8))];

    float acc[2][8][4];
    #pragma unroll
    for (int mt = 0; mt < 2; ++mt)
        #pragma unroll
        for (int nt = 0; nt < 8; ++nt)
            #pragma unroll
            for (int e = 0; e < 4; ++e) acc[mt][nt][e] = 0.f;

    #pragma unroll
    for (int kc = 0; kc < 3; ++kc) {
        const int k0 = kc * 16 + lt * 2;
        // ---- A fragments direct from global (hi/lo) ----
        uint32_t Ah[2][4], Al[2][4];
        #pragma unroll
        for (int mt = 0; mt < 2; ++mt) {
            const int r0 = (mt == 0) ? ar0 : ar1;
            float2 p0a = *(const float2*)(At + (size_t)r0 * F2Dd + k0);
            float2 p0b = *(const float2*)(At + (size_t)(r0 + 8) * F2Dd + k0);
            float2 p1a, p1b;
            if (kc < 2) {
                p1a = *(const float2*)(At + (size_t)r0 * F2Dd + k0 + 8);
                p1b = *(const float2*)(At + (size_t)(r0 + 8) * F2Dd + k0 + 8);
            } else {
                if (lt < 2) {
                    p1a = *(const float2*)(At + (size_t)r0 * F2Dd + k0 + 8);
                    p1b = *(const float2*)(At + (size_t)(r0 + 8) * F2Dd + k0 + 8);
                } else if (lt == 2) {   // k = 44,45 -> (sep, 0)
                    p1a = make_float2(sepv[mt * 2], 0.f);
                    p1b = make_float2(sepv[mt * 2 + 1], 0.f);
                } else {                // k = 46,47 -> zeros
                    p1a = make_float2(0.f, 0.f);
                    p1b = make_float2(0.f, 0.f);
                }
            }
            hilo2(p0a, Ah[mt][0], Al[mt][0]);
            hilo2(p0b, Ah[mt][1], Al[mt][1]);
            hilo2(p1a, Ah[mt][2], Al[mt][2]);
            hilo2(p1b, Ah[mt][3], Al[mt][3]);
        }
        // ---- B fragments: load one nt2 pair, consume immediately ----
        #pragma unroll
        for (int nt2 = 0; nt2 < 4; ++nt2) {
            uint32_t rh[4], rl[4];
            ldm_x4(rh, sbB + bRow + (uint32_t)(nt2 * 16) * ARS + kc * 32);
            ldm_x4(rl, sbB + 64 * ARS + bRow + (uint32_t)(nt2 * 16) * ARS + kc * 32);
            #pragma unroll
            for (int h = 0; h < 2; ++h) {
                const int nt = nt2 * 2 + h;
                uint32_t B2h[2] = { rh[h * 2], rh[h * 2 + 1] };
                uint32_t B2l[2] = { rl[h * 2], rl[h * 2 + 1] };
                #pragma unroll
                for (int mt = 0; mt < 2; ++mt) {
                    mma_bf16(acc[mt][nt], Ah[mt], B2h);
                    mma_bf16(acc[mt][nt], Al[mt], B2h);
                    mma_bf16(acc[mt][nt], Ah[mt], B2l);
                }
            }
        }
    }

    // ---- direct epilogue from D fragments ----
    const float* eRb = g_eR + ((size_t)bt * Ld) * Kd;
    float* outb = out + rowbase * Kd;
    #pragma unroll
    for (int mt = 0; mt < 2; ++mt) {
        const int r0 = (mt == 0) ? ar0 : ar1;     // local row (j - j0)
        const int jA = j0 + r0;
        const int jB = jA + 8;
        #pragma unroll
        for (int nt = 0; nt < 8; ++nt) {
            const int col = nt * 8 + lt * 2;
            float2 b2 = *(const float2*)(sBase + col);
            float2 eA = *(const float2*)(eRb + (size_t)jA * Kd + col);
            float2 eB = *(const float2*)(eRb + (size_t)jB * Kd + col);
            float v0 = acc[mt][nt][0] + b2.x + eA.x;
            float v1 = acc[mt][nt][1] + b2.y + eA.y;
            float v2 = acc[mt][nt][2] + b2.x + eB.x;
            float v3 = acc[mt][nt][3] + b2.y + eB.y;
            if (bt == 0 && nt >= 4) {
                float2 pA = *(const float2*)(g_pe + jA * 32 + (col - 32));
                float2 pB = *(const float2*)(g_pe + jB * 32 + (col - 32));
                v0 += pA.x; v1 += pA.y; v2 += pB.x; v3 += pB.y;
            }
            __stcs((float2*)(outb + (size_t)r0 * Kd + col), make_float2(v0, v1));
            __stcs((float2*)(outb + (size_t)(r0 + 8) * Kd + col), make_float2(v2, v3));
        }
    }
}

// ---------------------------------------------------------------------------
extern "C" void kernel_launch(void* const* d_in, const int* in_sizes, int n_in,
                              void* d_out, int out_size) {
    const float* t1d = (const float*)d_in[0];
    const float* t2d = (const float*)d_in[1];
    const float* p1w = (const float*)d_in[2];
    const float* p1b = (const float*)d_in[3];
    const float* c1w = (const float*)d_in[4];
    const float* c2w = (const float*)d_in[5];
    const float* pw  = (const float*)d_in[6];
    const float* pb  = (const float*)d_in[7];
    float* out = (float*)d_out;
    (void)in_sizes; (void)n_in; (void)out_size;

    k_tower<<<128, 512>>>(t1d, p1w, p1b, c1w, c2w, pw, pb);
    k_pair<<<8192, 128>>>(t2d, pw, out);
}